// round 7
// baseline (speedup 1.0000x reference)
#include <cuda_runtime.h>
#include <cuda_fp16.h>

// ForwardWarp: forward splatting with Gaussian softmax weights.
// img, counts: (8,1,720,1280) f32; flo: (8,2,720,1280) f32 (ch0 = y shifts W axis, ch1 = x shifts H axis)
// out: [0:S) = img_warp / (one_warp + eps), [S:2S) = one_warp
//
// Scratch: 4 copies keyed by (ix1&1, iy1&1). Each copy tiles the (padded) grid into
// 2x2-cell blocks of 16B: slots [ (r0,y0), (r0,y0+1), (r0+1,y0), (r0+1,y0+1) ], each
// slot an f16x2 {img*cw, cw}. An interior pixel's whole 2x2 tap footprint = ONE
// 16B-aligned block in its parity copy -> one branchless red.global.add.noftz.v4.f16x2.
// A cell's ~4 contributions land in 4 distinct copies (tap role fixes parity) -> ~1 add
// per slot -> only fp16 packing error (~2.8e-4, validated in R6). Normalize gathers the
// 4 copies in fp32, writes outputs, zero-restores scratch (BSS invariant, no memset).
// 4 batch-chunks keep live scratch L2-resident.

static constexpr int N_ = 8;
static constexpr int H_ = 720;
static constexpr int W_ = 1280;
static constexpr int S_ = N_ * H_ * W_;    // 7,372,800
static constexpr float EPS_ = 1e-6f;

static constexpr int CHUNKS_ = 4;          // 2 images per chunk
static constexpr int PC_ = S_ / CHUNKS_;   // 1,843,200 pixels per chunk

// Block grid per copy per image: rows of blocks cover cell rows [-1..720] as needed.
static constexpr int BR_ = 361;            // block rows
static constexpr int BC_ = 641;            // block cols
static constexpr int BLK_PER_IMG_ = BR_ * BC_;          // 231,401
static constexpr int BLK_TOTAL_ = 4 * N_ * BLK_PER_IMG_; // 7,404,832 blocks * 16B = 118.5MB

__device__ __align__(16) uint4 g_blk[BLK_TOTAL_];   // BSS: starts zero; restored each launch

__device__ __forceinline__ void red_v4h2(uint4* p, unsigned int s0, unsigned int s1,
                                         unsigned int s2, unsigned int s3) {
    asm volatile("red.global.add.noftz.v4.f16x2 [%0], {%1, %2, %3, %4};"
                 :: "l"(p), "r"(s0), "r"(s1), "r"(s2), "r"(s3) : "memory");
}
__device__ __forceinline__ void red_h2(unsigned int* p, unsigned int r) {
    asm volatile("red.global.add.noftz.f16x2 [%0], %1;"
                 :: "l"(p), "r"(r) : "memory");
}
__device__ __forceinline__ unsigned int pack_h2(float a, float b) {
    __half2 h = __float22half2_rn(make_float2(a, b));
    return *reinterpret_cast<unsigned int*>(&h);
}
__device__ __forceinline__ float2 unpack_h2(unsigned int u) {
    return __half22float2(*reinterpret_cast<__half2*>(&u));
}

__global__ void __launch_bounds__(256) splat_kernel(
    const float* __restrict__ img,
    const float* __restrict__ counts,
    const float* __restrict__ flo,
    int chunk)
{
    int idx = chunk * PC_ + blockIdx.x * blockDim.x + threadIdx.x;

    int w  = idx % W_;
    int hw = idx / W_;
    int h  = hw % H_;
    int n  = hw / H_;

    // flo layout: (N, 2, H, W). channel 0 = y (shifts W axis), channel 1 = x (shifts H axis)
    int flo_base = ((n * 2) * H_ + h) * W_ + w;
    float y = flo[flo_base];
    float x = flo[flo_base + H_ * W_];

    float im = img[idx];
    float c  = counts[idx];

    float x1 = floorf(x);
    float y1 = floorf(y);
    float fx = x - x1;            // (x - x1) in [0,1)
    float fy = y - y1;
    float gx = fx - 1.0f;         // (x - x2)
    float gy = fy - 1.0f;

    float dx1 = fx * fx, dx2 = gx * gx;
    float dy1 = fy * fy, dy2 = gy * gy;

    float w11 = __expf(-(dx1 + dy1));
    float w12 = __expf(-(dx1 + dy2));
    float w21 = __expf(-(dx2 + dy1));
    float w22 = __expf(-(dx2 + dy2));
    float inv = 1.0f / (w11 + w12 + w21 + w22);

    float cinv = c * inv;
    float wa1 = w11 * cinv, wb1 = w12 * cinv;   // row ix1: cols iy1, iy2
    float wa2 = w21 * cinv, wb2 = w22 * cinv;   // row ix2

    int ix1 = (int)x1 + h;       // top tap row
    int iy1 = (int)y1 + w;       // left tap col

    // whole 2x2 footprint outside? (any valid tap requires ix1 in [-1,H-1], iy1 in [-1,W-1])
    if (ix1 < -1 || ix1 > H_ - 1 || iy1 < -1 || iy1 > W_ - 1) return;

    int pr = ix1 & 1;            // note: -1 & 1 == 1
    int pc = iy1 & 1;
    int R = (ix1 + pr) >> 1;     // block row (origin 2R - pr == ix1)
    int Y = (iy1 + pc) >> 1;

    uint4* blk = g_blk + (((pr * 2 + pc) * N_ + n) * BR_ + R) * BC_ + Y;

    unsigned int s0 = pack_h2(im * wa1, wa1);
    unsigned int s1 = pack_h2(im * wb1, wb1);
    unsigned int s2 = pack_h2(im * wa2, wa2);
    unsigned int s3 = pack_h2(im * wb2, wb2);

    bool interior = (ix1 >= 0) & (ix1 <= H_ - 2) & (iy1 >= 0) & (iy1 <= W_ - 2);
    if (interior) {
        red_v4h2(blk, s0, s1, s2, s3);      // one branchless 16B RED
    } else {
        // boundary: scalar REDs for valid taps only (same block/slots)
        unsigned int* cell = reinterpret_cast<unsigned int*>(blk);
        bool r1 = (ix1 >= 0);                // ix1 <= H_-1 already guaranteed
        bool r2 = (ix1 + 1 <= H_ - 1);       // ix1 >= -1 guaranteed
        bool c1 = (iy1 >= 0);
        bool c2 = (iy1 + 1 <= W_ - 1);
        if (r1 && c1) red_h2(cell + 0, s0);
        if (r1 && c2) red_h2(cell + 1, s1);
        if (r2 && c1) red_h2(cell + 2, s2);
        if (r2 && c2) red_h2(cell + 3, s3);
    }
}

// Per cell: gather its slot from each of the 4 copies, sum in fp32, write outputs,
// zero-restore exactly the slots read (every non-pad slot maps to exactly one cell
// -> race-free; pad slots are never written so stay zero).
static constexpr int NT_ = 256;
static constexpr int NCPT_ = 8;    // cells per thread

__global__ void __launch_bounds__(256) normalize_kernel(float* __restrict__ out, int chunk)
{
    int base = chunk * PC_ + blockIdx.x * (NT_ * NCPT_) + threadIdx.x;

    #pragma unroll
    for (int k = 0; k < NCPT_; k++) {
        int cidx = base + k * NT_;
        int yy = cidx % W_;
        int t  = cidx / W_;
        int rr = t % H_;
        int nn = t / H_;

        float num = 0.f, den = 0.f;
        #pragma unroll
        for (int pr = 0; pr < 2; pr++) {
            #pragma unroll
            for (int pc = 0; pc < 2; pc++) {
                int R = (rr + pr) >> 1;
                int Y = (yy + pc) >> 1;
                int inner = ((rr + pr) & 1) * 2 + ((yy + pc) & 1);
                unsigned int* cell = reinterpret_cast<unsigned int*>(
                    g_blk + (((pr * 2 + pc) * N_ + nn) * BR_ + R) * BC_ + Y) + inner;
                unsigned int u = *cell;
                *cell = 0u;
                float2 f = unpack_h2(u);
                num += f.x;
                den += f.y;
            }
        }
        out[cidx]      = num / (den + EPS_);
        out[S_ + cidx] = den;
    }
}

extern "C" void kernel_launch(void* const* d_in, const int* in_sizes, int n_in,
                              void* d_out, int out_size)
{
    const float* img    = (const float*)d_in[0];
    const float* counts = (const float*)d_in[1];
    const float* flo    = (const float*)d_in[2];
    float* out = (float*)d_out;

    int splat_blocks = PC_ / 256;             // 7200
    int norm_blocks  = PC_ / (NT_ * NCPT_);   // 900

    for (int chunk = 0; chunk < CHUNKS_; chunk++) {
        splat_kernel<<<splat_blocks, 256>>>(img, counts, flo, chunk);
        normalize_kernel<<<norm_blocks, NT_>>>(out, chunk);
    }
}

// round 8
// speedup vs baseline: 4.9847x; 4.9847x over previous
#include <cuda_runtime.h>
#include <cuda_fp16.h>

// ForwardWarp: forward splatting with Gaussian softmax weights.
// img, counts: (8,1,720,1280) f32; flo: (8,2,720,1280) f32 (ch0 = y shifts W, ch1 = x shifts H)
// out: [0:S) = img_warp / (one_warp + eps), [S:2S) = one_warp
//
// Splat model: time ~ distinct 32B sectors touched by REDs. One branchless
// red.global.add.noftz.v4.f16x2 per pixel = 1 sector. Scratch = 4 parity copies
// (pr=ix1&1, pc=iy1&1), each a rowpair-interleaved grid: pair P holds rows
// {2P-pr? see below} with words [.. c(r0,y), c(r1,y), c(r0,y+1), c(r1,y+1) ..].
//   pr=0: P = ix1>>1,      rows {2P, 2P+1}
//   pr=1: P = (ix1+1)>>1,  rows {2P-1, 2P}   (P=0 holds pad row -1; P=360 holds pad row 720)
// word-in-pair for (row dr, col yy) = 2*yy + dr + 2*pc  (pc shift makes odd iy1 16B-aligned;
// col -1 / 1280 land in pad words). All boundary taps hit pads -> no edge path.
// Copies sized for a 2-image chunk, reused across 4 chunks; cudaMemsetAsync re-zeroes
// after each normalize (scratch L2-resident). Normalize: all-vector loads (uint4/uint2),
// no scratch stores -> full MLP; sums 4 copies in fp32.

static constexpr int N_ = 8;
static constexpr int H_ = 720;
static constexpr int W_ = 1280;
static constexpr int S_ = N_ * H_ * W_;     // 7,372,800
static constexpr float EPS_ = 1e-6f;

static constexpr int CHUNKS_ = 4;           // 2 images per chunk
static constexpr int PC_ = S_ / CHUNKS_;    // 1,843,200 pixels per chunk

static constexpr int NP_ = 361;             // pair-rows per copy (covers pads)
static constexpr int WPAD_ = 2564;          // words per pair-row (2*1280 + 2 shift + 2 pad), 16B multiple
static constexpr int COPY_WORDS_ = NP_ * WPAD_;            // 925,604 (per copy per image)
static constexpr int SCR_WORDS_ = 4 * 2 * COPY_WORDS_;     // 7,404,832 words = 29.6MB

__device__ __align__(16) unsigned int g_S[SCR_WORDS_];     // BSS zero; memset restores per chunk

__device__ __forceinline__ void red_v4h2(unsigned int* p, unsigned int s0, unsigned int s1,
                                         unsigned int s2, unsigned int s3) {
    asm volatile("red.global.add.noftz.v4.f16x2 [%0], {%1, %2, %3, %4};"
                 :: "l"(p), "r"(s0), "r"(s1), "r"(s2), "r"(s3) : "memory");
}
__device__ __forceinline__ unsigned int pack_h2(float a, float b) {
    __half2 h = __float22half2_rn(make_float2(a, b));
    return *reinterpret_cast<unsigned int*>(&h);
}
__device__ __forceinline__ float2 unpack_h2(unsigned int u) {
    return __half22float2(*reinterpret_cast<__half2*>(&u));
}

__global__ void __launch_bounds__(256) splat_kernel(
    const float* __restrict__ img,
    const float* __restrict__ counts,
    const float* __restrict__ flo,
    int chunk)
{
    int idx = chunk * PC_ + blockIdx.x * blockDim.x + threadIdx.x;

    int w  = idx % W_;
    int hw = idx / W_;
    int h  = hw % H_;
    int n  = hw / H_;
    int ni = n & 1;                 // image within chunk

    // flo layout: (N, 2, H, W). ch0 = y (shifts W axis), ch1 = x (shifts H axis)
    int flo_base = ((n * 2) * H_ + h) * W_ + w;
    float y = flo[flo_base];
    float x = flo[flo_base + H_ * W_];

    float im = img[idx];
    float c  = counts[idx];

    float x1 = floorf(x);
    float y1 = floorf(y);
    float fx = x - x1;
    float fy = y - y1;
    float gx = fx - 1.0f;
    float gy = fy - 1.0f;

    float dx1 = fx * fx, dx2 = gx * gx;
    float dy1 = fy * fy, dy2 = gy * gy;

    float w11 = __expf(-(dx1 + dy1));   // row ix1, col iy1
    float w12 = __expf(-(dx1 + dy2));   // row ix1, col iy2
    float w21 = __expf(-(dx2 + dy1));   // row ix2, col iy1
    float w22 = __expf(-(dx2 + dy2));   // row ix2, col iy2
    float inv = 1.0f / (w11 + w12 + w21 + w22);
    float cinv = c * inv;

    int ix1 = (int)x1 + h;
    int iy1 = (int)y1 + w;

    // whole footprint outside the (padded) grid?
    if (ix1 < -1 || ix1 > H_ - 1 || iy1 < -1 || iy1 > W_ - 1) return;

    int pr = ix1 & 1;                     // (-1 & 1) == 1
    int pc = iy1 & 1;
    int P  = (ix1 + pr) >> 1;             // pair-row, >= 0
    int wv = 2 * iy1 + 2 * pc;            // word within pair-row, >= 0

    unsigned int* p = g_S + ((((pr * 2 + pc) * 2 + ni) * NP_ + P) * WPAD_ + wv);

    // word order in pair: [ (r1,c1), (r2,c1), (r1,c2), (r2,c2) ]
    red_v4h2(p,
             pack_h2(im * (w11 * cinv), w11 * cinv),
             pack_h2(im * (w21 * cinv), w21 * cinv),
             pack_h2(im * (w12 * cinv), w12 * cinv),
             pack_h2(im * (w22 * cinv), w22 * cinv));
}

// One thread per 2x2 output tile: rows (2r, 2r+1), cols (2Y, 2Y+1), image ni.
// All scratch accesses are vector loads (no stores; memset restores zeros).
__global__ void __launch_bounds__(256) normalize_kernel(float* __restrict__ out, int chunk)
{
    int t = blockIdx.x * blockDim.x + threadIdx.x;   // 0 .. 460799 per chunk
    int Y  = t % (W_ / 2);
    int rm = t / (W_ / 2);
    int r  = rm % (H_ / 2);
    int ni = rm / (H_ / 2);
    int n  = chunk * 2 + ni;

    const unsigned int* c00 = g_S + ((0 * 2 + ni) * NP_) * WPAD_;
    const unsigned int* c01 = g_S + ((1 * 2 + ni) * NP_) * WPAD_;
    const unsigned int* c10 = g_S + ((2 * 2 + ni) * NP_) * WPAD_;
    const unsigned int* c11 = g_S + ((3 * 2 + ni) * NP_) * WPAD_;

    int rowr  = r * WPAD_;
    int rowr1 = rowr + WPAD_;
    int q = 4 * Y;

    // copy(0,0): pair r, words [q .. q+3]  -> cells (2r,2Y),(2r+1,2Y),(2r,2Y+1),(2r+1,2Y+1)
    uint4 v  = *reinterpret_cast<const uint4*>(c00 + rowr + q);
    // copy(0,1): pair r, words [q+2 .. q+5]
    uint2 u0 = *reinterpret_cast<const uint2*>(c01 + rowr + q + 2);   // (2r,2Y),(2r+1,2Y)
    uint2 u1 = *reinterpret_cast<const uint2*>(c01 + rowr + q + 4);   // (2r,2Y+1),(2r+1,2Y+1)
    // copy(1,0): pair r (rows 2r-1,2r) odd words; pair r+1 (rows 2r+1,2r+2) even words
    uint4 a  = *reinterpret_cast<const uint4*>(c10 + rowr + q);       // a.y=(2r,2Y), a.w=(2r,2Y+1)
    uint4 b  = *reinterpret_cast<const uint4*>(c10 + rowr1 + q);      // b.x=(2r+1,2Y), b.z=(2r+1,2Y+1)
    // copy(1,1): shifted versions
    uint2 e0 = *reinterpret_cast<const uint2*>(c11 + rowr + q + 2);   // e0.y=(2r,2Y)
    uint2 e1 = *reinterpret_cast<const uint2*>(c11 + rowr + q + 4);   // e1.y=(2r,2Y+1)
    uint2 f0 = *reinterpret_cast<const uint2*>(c11 + rowr1 + q + 2);  // f0.x=(2r+1,2Y)
    uint2 f1 = *reinterpret_cast<const uint2*>(c11 + rowr1 + q + 4);  // f1.x=(2r+1,2Y+1)

    // cell (2r, 2Y):    v.x + u0.x + a.y + e0.y
    // cell (2r+1, 2Y):  v.y + u0.y + b.x + f0.x
    // cell (2r, 2Y+1):  v.z + u1.x + a.w + e1.y
    // cell (2r+1,2Y+1): v.w + u1.y + b.z + f1.x
    float2 s00 = unpack_h2(v.x), s00b = unpack_h2(u0.x), s00c = unpack_h2(a.y), s00d = unpack_h2(e0.y);
    float2 s10 = unpack_h2(v.y), s10b = unpack_h2(u0.y), s10c = unpack_h2(b.x), s10d = unpack_h2(f0.x);
    float2 s01 = unpack_h2(v.z), s01b = unpack_h2(u1.x), s01c = unpack_h2(a.w), s01d = unpack_h2(e1.y);
    float2 s11 = unpack_h2(v.w), s11b = unpack_h2(u1.y), s11c = unpack_h2(b.z), s11d = unpack_h2(f1.x);

    float num00 = (s00.x + s00b.x) + (s00c.x + s00d.x);
    float den00 = (s00.y + s00b.y) + (s00c.y + s00d.y);
    float num10 = (s10.x + s10b.x) + (s10c.x + s10d.x);
    float den10 = (s10.y + s10b.y) + (s10c.y + s10d.y);
    float num01 = (s01.x + s01b.x) + (s01c.x + s01d.x);
    float den01 = (s01.y + s01b.y) + (s01c.y + s01d.y);
    float num11 = (s11.x + s11b.x) + (s11c.x + s11d.x);
    float den11 = (s11.y + s11b.y) + (s11c.y + s11d.y);

    int o0 = ((n * H_) + 2 * r) * W_ + 2 * Y;       // row 2r
    int o1 = o0 + W_;                                // row 2r+1

    *reinterpret_cast<float2*>(out + o0)      = make_float2(num00 / (den00 + EPS_), num01 / (den01 + EPS_));
    *reinterpret_cast<float2*>(out + o1)      = make_float2(num10 / (den10 + EPS_), num11 / (den11 + EPS_));
    *reinterpret_cast<float2*>(out + S_ + o0) = make_float2(den00, den01);
    *reinterpret_cast<float2*>(out + S_ + o1) = make_float2(den10, den11);
}

extern "C" void kernel_launch(void* const* d_in, const int* in_sizes, int n_in,
                              void* d_out, int out_size)
{
    const float* img    = (const float*)d_in[0];
    const float* counts = (const float*)d_in[1];
    const float* flo    = (const float*)d_in[2];
    float* out = (float*)d_out;

    void* scr = nullptr;
    cudaGetSymbolAddress(&scr, g_S);

    int splat_blocks = PC_ / 256;                    // 7200
    int norm_blocks  = (PC_ / 4) / 256;              // 1800 (one thread per 2x2 tile)

    for (int chunk = 0; chunk < CHUNKS_; chunk++) {
        splat_kernel<<<splat_blocks, 256>>>(img, counts, flo, chunk);
        normalize_kernel<<<norm_blocks, 256>>>(out, chunk);
        // restore zeros for the next chunk / next graph replay (BSS gives the first)
        cudaMemsetAsync(scr, 0, (size_t)SCR_WORDS_ * sizeof(unsigned int));
    }
}